// round 1
// baseline (speedup 1.0000x reference)
#include <cuda_runtime.h>
#include <cstdint>

#define N_ENTITIES 100000
#define N_USERS    50000
#define N_ITEMS    30000
#define D          64
#define N_REL      16
#define N_FACTORS  4
#define N_CLUSTERS 4
#define N_EDGES    1500000
#define NNZ_IM     1000000
#define NNZ_ICM    1000000
#define N_HOPS     2
#define TMP        0.2f

// ---------------- scratch (static device globals; no allocation) ----------------
__device__ float g_att [N_ENTITIES * N_REL];    // per-entity relation softmax
__device__ float g_ucls[N_USERS * N_CLUSTERS];  // per-user cluster softmax
__device__ float g_e   [N_ENTITIES * D];        // normalized entity emb (hop output)
__device__ float g_eagg[N_ENTITIES * D];        // entity aggregation buffer
__device__ float g_u   [N_USERS * D];           // normalized user emb (hop output)
__device__ float g_uagg[N_USERS * D];           // user aggregation buffer
__device__ float g_relsum[D];                   // relation_emb.sum(0)

// ---------------- helpers ----------------
__device__ __forceinline__ void red_add_v4(float* p, float4 v) {
    asm volatile("red.global.add.v4.f32 [%0], {%1,%2,%3,%4};"
                 :: "l"(p), "f"(v.x), "f"(v.y), "f"(v.z), "f"(v.w)
                 : "memory");
}

// ---------------- kernels ----------------

__global__ void zero_kernel(float4* __restrict__ a, int n4) {
    int i = blockIdx.x * blockDim.x + threadIdx.x;
    if (i < n4) a[i] = make_float4(0.f, 0.f, 0.f, 0.f);
}

__global__ void relsum_kernel(const float* __restrict__ rel, float* __restrict__ out) {
    int k = threadIdx.x;  // 64 threads
    float s = 0.f;
#pragma unroll
    for (int r = 0; r < N_REL; r++) s += rel[r * D + k];
    out[k] = s;
}

// per-entity: att[i,:] = softmax(e[i] @ rel^T)
__global__ void att_kernel(const float* __restrict__ e, const float* __restrict__ rel,
                           float* __restrict__ att, int n) {
    __shared__ float s_rel[N_REL * D];
    for (int i = threadIdx.x; i < N_REL * D; i += blockDim.x) s_rel[i] = rel[i];
    __syncthreads();
    int i = blockIdx.x * blockDim.x + threadIdx.x;
    if (i >= n) return;
    const float4* row = (const float4*)(e + (size_t)i * D);
    float acc[N_REL];
#pragma unroll
    for (int r = 0; r < N_REL; r++) acc[r] = 0.f;
#pragma unroll
    for (int k = 0; k < D / 4; k++) {
        float4 ev = row[k];
#pragma unroll
        for (int r = 0; r < N_REL; r++) {
            float4 rv = ((const float4*)(s_rel + r * D))[k];
            acc[r] += ev.x * rv.x + ev.y * rv.y + ev.z * rv.z + ev.w * rv.w;
        }
    }
    float mx = acc[0];
#pragma unroll
    for (int r = 1; r < N_REL; r++) mx = fmaxf(mx, acc[r]);
    float sum = 0.f;
#pragma unroll
    for (int r = 0; r < N_REL; r++) { acc[r] = expf(acc[r] - mx); sum += acc[r]; }
    float inv = 1.f / sum;
#pragma unroll
    for (int r = 0; r < N_REL; r++) att[(size_t)i * N_REL + r] = acc[r] * inv;
}

// per-user: ucls[u,:] = softmax(u_emb[u] @ usr_cls_w^T)
__global__ void ucls_kernel(const float* __restrict__ u, const float* __restrict__ w,
                            float* __restrict__ ucls, int n) {
    __shared__ float sw[N_CLUSTERS * D];
    for (int i = threadIdx.x; i < N_CLUSTERS * D; i += blockDim.x) sw[i] = w[i];
    __syncthreads();
    int i = blockIdx.x * blockDim.x + threadIdx.x;
    if (i >= n) return;
    const float4* row = (const float4*)(u + (size_t)i * D);
    float acc[N_CLUSTERS] = {0.f, 0.f, 0.f, 0.f};
#pragma unroll
    for (int k = 0; k < D / 4; k++) {
        float4 uv = row[k];
#pragma unroll
        for (int c = 0; c < N_CLUSTERS; c++) {
            float4 wv = ((const float4*)(sw + c * D))[k];
            acc[c] += uv.x * wv.x + uv.y * wv.y + uv.z * wv.z + uv.w * wv.w;
        }
    }
    float mx = fmaxf(fmaxf(acc[0], acc[1]), fmaxf(acc[2], acc[3]));
    float sum = 0.f;
#pragma unroll
    for (int c = 0; c < N_CLUSTERS; c++) { acc[c] = expf(acc[c] - mx); sum += acc[c]; }
    float inv = 1.f / sum;
#pragma unroll
    for (int c = 0; c < N_CLUSTERS; c++) ucls[(size_t)i * N_CLUSTERS + c] = acc[c] * inv;
}

// edge scatter: entity_agg[head] += e[tail] * rel[type] * (att[head,type]*imp)
// 16 threads per edge; each thread handles one float4 of the 64-dim row.
__global__ void edge_kernel(const float* __restrict__ e,
                            const int* __restrict__ head, const int* __restrict__ tail,
                            const int* __restrict__ etype, const float* __restrict__ eimp,
                            const float* __restrict__ att, const float* __restrict__ rel,
                            float* __restrict__ eagg, int n_edges) {
    __shared__ float s_rel[N_REL * D];
    for (int i = threadIdx.x; i < N_REL * D; i += blockDim.x) s_rel[i] = rel[i];
    __syncthreads();
    int gid  = blockIdx.x * blockDim.x + threadIdx.x;
    int edge = gid >> 4;
    int lane = gid & 15;
    if (edge >= n_edges) return;
    int h = head[edge], t = tail[edge], r = etype[edge];
    float s = att[(size_t)h * N_REL + r] * eimp[edge];
    float4 ev = ((const float4*)(e + (size_t)t * D))[lane];
    float4 rv = ((const float4*)(s_rel + r * D))[lane];
    float4 m = make_float4(ev.x * rv.x * s, ev.y * rv.y * s, ev.z * rv.z * s, ev.w * rv.w * s);
    red_add_v4(eagg + (size_t)h * D + lane * 4, m);
}

// im scatter: user_agg[row] += im_vals * e[col]
__global__ void im_kernel(const float* __restrict__ e,
                          const float* __restrict__ vals,
                          const int* __restrict__ rows, const int* __restrict__ cols,
                          float* __restrict__ uagg, int nnz) {
    int gid  = blockIdx.x * blockDim.x + threadIdx.x;
    int j    = gid >> 4;
    int lane = gid & 15;
    if (j >= nnz) return;
    int ro = rows[j], co = cols[j];
    float v = vals[j];
    float4 ev = ((const float4*)(e + (size_t)co * D))[lane];
    float4 m = make_float4(ev.x * v, ev.y * v, ev.z * v, ev.w * v);
    red_add_v4(uagg + (size_t)ro * D + lane * 4, m);
}

// icm scatter (fused dw einsum):
//   user_agg[row] += icm_vals * ucls[row,cls] * (e[col] * rel_sum)
__global__ void icm_kernel(const float* __restrict__ e,
                           const float* __restrict__ vals,
                           const int* __restrict__ rows, const int* __restrict__ cols,
                           const int* __restrict__ cls,
                           const float* __restrict__ ucls,
                           const float* __restrict__ relsum,
                           float* __restrict__ uagg, int nnz) {
    __shared__ float s_rs[D];
    if (threadIdx.x < D) s_rs[threadIdx.x] = relsum[threadIdx.x];
    __syncthreads();
    int gid  = blockIdx.x * blockDim.x + threadIdx.x;
    int j    = gid >> 4;
    int lane = gid & 15;
    if (j >= nnz) return;
    int ro = rows[j], co = cols[j], c = cls[j];
    float w = vals[j] * ucls[(size_t)ro * N_CLUSTERS + c];
    float4 ev = ((const float4*)(e + (size_t)co * D))[lane];
    float4 rs = ((const float4*)(s_rs))[lane];
    float4 m = make_float4(ev.x * rs.x * w, ev.y * rs.y * w, ev.z * rs.z * w, ev.w * rs.w * w);
    red_add_v4(uagg + (size_t)ro * D + lane * 4, m);
}

// normalize agg rows, write normalized to dst and accumulate into res.
// one warp per row, float2 per lane.
__global__ void norm_acc_kernel(const float* __restrict__ agg,
                                float* __restrict__ dst, float* __restrict__ res,
                                int n_rows) {
    int warp = (blockIdx.x * blockDim.x + threadIdx.x) >> 5;
    int lane = threadIdx.x & 31;
    if (warp >= n_rows) return;
    float2 v = ((const float2*)(agg + (size_t)warp * D))[lane];
    float ss = v.x * v.x + v.y * v.y;
#pragma unroll
    for (int o = 16; o; o >>= 1) ss += __shfl_xor_sync(0xffffffffu, ss, o);
    float nrm = sqrtf(ss);
    float inv = 1.f / fmaxf(nrm, 1e-12f);
    float2 o2 = make_float2(v.x * inv, v.y * inv);
    ((float2*)(dst + (size_t)warp * D))[lane] = o2;
    float2* rp = (float2*)(res + (size_t)warp * D);
    float2 cur = rp[lane];
    cur.x += o2.x; cur.y += o2.y;
    rp[lane] = cur;
}

// cor_loss from disen_weight_att (4x16) — tiny, 1 thread.
__global__ void cor_kernel(const float* __restrict__ dw, float* __restrict__ out) {
    float nt[N_FACTORS][N_REL];
#pragma unroll
    for (int c = 0; c < N_FACTORS; c++) {
        float ss = 0.f;
#pragma unroll
        for (int k = 0; k < N_REL; k++) { float x = dw[c * N_REL + k]; ss += x * x; }
        float inv = 1.f / fmaxf(sqrtf(ss), 1e-12f);
#pragma unroll
        for (int k = 0; k < N_REL; k++) nt[c][k] = dw[c * N_REL + k] * inv;
    }
    float loss = 0.f;
#pragma unroll
    for (int i = 0; i < N_FACTORS; i++) {
        float ssum = 0.f, diag = 0.f;
#pragma unroll
        for (int j = 0; j < N_FACTORS; j++) {
            float dot = 0.f;
#pragma unroll
            for (int k = 0; k < N_REL; k++) dot += nt[i][k] * nt[j][k];
            float s = expf(dot / TMP);
            ssum += s;
            if (i == j) diag = s;
        }
        loss -= logf(diag / ssum);
    }
    out[0] = loss;
}

// ---------------- launch ----------------
extern "C" void kernel_launch(void* const* d_in, const int* in_sizes, int n_in,
                              void* d_out, int out_size) {
    const float* user_emb     = (const float*)d_in[0];
    const float* entity_emb   = (const float*)d_in[1];
    /* d_in[2] latent_emb unused */
    const float* relation_emb = (const float*)d_in[3];
    const float* disen        = (const float*)d_in[4];
    const float* usr_cls_w    = (const float*)d_in[5];
    const float* edge_imp     = (const float*)d_in[6];
    const float* im_vals      = (const float*)d_in[7];
    const float* icm_vals     = (const float*)d_in[8];
    const int*   edge_index   = (const int*)d_in[9];
    const int*   edge_type    = (const int*)d_in[10];
    const int*   im_rows      = (const int*)d_in[11];
    const int*   im_cols      = (const int*)d_in[12];
    const int*   icm_cls      = (const int*)d_in[13];
    const int*   icm_rows     = (const int*)d_in[14];
    const int*   icm_cols     = (const int*)d_in[15];

    float* out     = (float*)d_out;
    float* out_ent = out;
    float* out_usr = out + (size_t)N_ENTITIES * D;
    float* out_cor = out + (size_t)N_ENTITIES * D + (size_t)N_USERS * D;

    float *p_att, *p_ucls, *p_e, *p_eagg, *p_u, *p_uagg, *p_relsum;
    cudaGetSymbolAddress((void**)&p_att, g_att);
    cudaGetSymbolAddress((void**)&p_ucls, g_ucls);
    cudaGetSymbolAddress((void**)&p_e, g_e);
    cudaGetSymbolAddress((void**)&p_eagg, g_eagg);
    cudaGetSymbolAddress((void**)&p_u, g_u);
    cudaGetSymbolAddress((void**)&p_uagg, g_uagg);
    cudaGetSymbolAddress((void**)&p_relsum, g_relsum);

    // residual init: res = input embeddings
    cudaMemcpyAsync(out_ent, entity_emb, sizeof(float) * (size_t)N_ENTITIES * D,
                    cudaMemcpyDeviceToDevice);
    cudaMemcpyAsync(out_usr, user_emb, sizeof(float) * (size_t)N_USERS * D,
                    cudaMemcpyDeviceToDevice);

    relsum_kernel<<<1, 64>>>(relation_emb, p_relsum);

    const int TPB = 256;
    const float* e_in = entity_emb;
    const float* u_in = user_emb;

    for (int hop = 0; hop < N_HOPS; hop++) {
        att_kernel<<<(N_ENTITIES + TPB - 1) / TPB, TPB>>>(e_in, relation_emb, p_att, N_ENTITIES);
        ucls_kernel<<<(N_USERS + TPB - 1) / TPB, TPB>>>(u_in, usr_cls_w, p_ucls, N_USERS);

        int ne4 = N_ENTITIES * D / 4;
        int nu4 = N_USERS * D / 4;
        zero_kernel<<<(ne4 + TPB - 1) / TPB, TPB>>>((float4*)p_eagg, ne4);
        zero_kernel<<<(nu4 + TPB - 1) / TPB, TPB>>>((float4*)p_uagg, nu4);

        long long ethreads = (long long)N_EDGES * 16;
        edge_kernel<<<(unsigned)((ethreads + TPB - 1) / TPB), TPB>>>(
            e_in, edge_index, edge_index + N_EDGES, edge_type, edge_imp,
            p_att, relation_emb, p_eagg, N_EDGES);

        long long imthreads = (long long)NNZ_IM * 16;
        im_kernel<<<(unsigned)((imthreads + TPB - 1) / TPB), TPB>>>(
            e_in, im_vals, im_rows, im_cols, p_uagg, NNZ_IM);

        long long icmthreads = (long long)NNZ_ICM * 16;
        icm_kernel<<<(unsigned)((icmthreads + TPB - 1) / TPB), TPB>>>(
            e_in, icm_vals, icm_rows, icm_cols, icm_cls, p_ucls, p_relsum,
            p_uagg, NNZ_ICM);

        norm_acc_kernel<<<(N_ENTITIES * 32 + TPB - 1) / TPB, TPB>>>(p_eagg, p_e, out_ent, N_ENTITIES);
        norm_acc_kernel<<<(N_USERS * 32 + TPB - 1) / TPB, TPB>>>(p_uagg, p_u, out_usr, N_USERS);

        e_in = p_e;
        u_in = p_u;
    }

    cor_kernel<<<1, 1>>>(disen, out_cor);
}